// round 13
// baseline (speedup 1.0000x reference)
#include <cuda_runtime.h>
#include <cuda_bf16.h>
#include <cstdint>

#define NN 100000
#define EE 1600000
#define D  128
#define OD 64
#define NG 512
#define SCAN_BLK 512
#define NBLK ((NN + SCAN_BLK - 1) / SCAN_BLK)   // 196

// Scratch (device globals: allocation-free)
__device__ __align__(16) __nv_bfloat16 g_bufA[NN * D];  // raw h_hat (bf16)
__device__ __align__(16) __nv_bfloat16 g_Ahi[NN * D];   // GEMM A input hi
__device__ __align__(16) __nv_bfloat16 g_Alo[NN * D];   // GEMM A input lo
__device__ float g_dinv[NN];
__device__ __align__(16) float g_pool[NG * D];   // zeroed by k_final (self-clean)
__device__ int   g_cnt[NN];                      // zeroed by k_scan3 (self-clean)
__device__ int   g_pos[NN];
__device__ int   g_rowptr[NN + 1];
__device__ int   g_blksum[256];
__device__ int   g_csr[EE];
// Pre-transposed, bf16-split weights: [n*128 + k]
__device__ __align__(16) __nv_bfloat16 g_W1hi[D * D];
__device__ __align__(16) __nv_bfloat16 g_W1lo[D * D];
__device__ __align__(16) __nv_bfloat16 g_W2hi[D * D];
__device__ __align__(16) __nv_bfloat16 g_W2lo[D * D];

__device__ __forceinline__ void red_add_v4(float* addr, float4 v) {
    asm volatile("red.global.add.v4.f32 [%0], {%1,%2,%3,%4};"
                 :: "l"(__cvta_generic_to_global(addr)),
                    "f"(v.x), "f"(v.y), "f"(v.z), "f"(v.w)
                 : "memory");
}

__device__ __forceinline__ uint32_t pack_bf2(float a, float b) {
    __nv_bfloat162 t = __floats2bfloat162_rn(a, b);
    return *reinterpret_cast<uint32_t*>(&t);
}

// ---------------------------------------------------------------------------
__global__ void k_count(const int* __restrict__ ei) {
    int i = blockIdx.x * blockDim.x + threadIdx.x;
    if (i < EE) atomicAdd(&g_cnt[ei[EE + i]], 1);
}

// x split + W transpose/split (side stream; disjoint from CSR chain)
#define NB_PREPX ((NN * D / 4 + 255) / 256)  // 12500
#define NB_PREPW 128

__global__ void k_prepxw(const float* __restrict__ x,
                         const float* __restrict__ W1, const float* __restrict__ W2) {
    int b = blockIdx.x;
    if (b < NB_PREPX) {
        int i = b * 256 + threadIdx.x;   // float4 index
        if (i < NN * D / 4) {
            float4 v = reinterpret_cast<const float4*>(x)[i];
            float hx = __bfloat162float(__float2bfloat16_rn(v.x));
            float hy = __bfloat162float(__float2bfloat16_rn(v.y));
            float hz = __bfloat162float(__float2bfloat16_rn(v.z));
            float hw = __bfloat162float(__float2bfloat16_rn(v.w));
            reinterpret_cast<uint2*>(g_Ahi)[i] =
                make_uint2(pack_bf2(v.x, v.y), pack_bf2(v.z, v.w));
            reinterpret_cast<uint2*>(g_Alo)[i] =
                make_uint2(pack_bf2(v.x - hx, v.y - hy), pack_bf2(v.z - hz, v.w - hw));
        }
    } else {
        int id = (b - NB_PREPX) * 256 + threadIdx.x;   // 0..32767
        int w = id >> 14;
        int r = id & 16383;
        int k = r >> 7, n = r & 127;
        float v = (w ? W2 : W1)[k * D + n];
        __nv_bfloat16 hi = __float2bfloat16_rn(v);
        __nv_bfloat16 lo = __float2bfloat16_rn(v - __bfloat162float(hi));
        (w ? g_W2hi : g_W1hi)[n * D + k] = hi;
        (w ? g_W2lo : g_W1lo)[n * D + k] = lo;
    }
}

// ---------------------------------------------------------------------------
__global__ void k_scan1() {
    __shared__ int s[SCAN_BLK];
    int gid = blockIdx.x * SCAN_BLK + threadIdx.x;
    int v = (gid < NN) ? g_cnt[gid] : 0;
    s[threadIdx.x] = v;
    __syncthreads();
    #pragma unroll
    for (int off = 1; off < SCAN_BLK; off <<= 1) {
        int t = (threadIdx.x >= off) ? s[threadIdx.x - off] : 0;
        __syncthreads();
        s[threadIdx.x] += t;
        __syncthreads();
    }
    if (gid < NN) g_rowptr[gid + 1] = s[threadIdx.x];
    if (threadIdx.x == SCAN_BLK - 1) g_blksum[blockIdx.x] = s[threadIdx.x];
    if (gid == 0) g_rowptr[0] = 0;
}

// scan3: per-block blksum prefix (merged scan2), rowptr/cursors/dinv; self-clean.
__global__ void k_scan3() {
    __shared__ int red[16];
    __shared__ int pref;
    int t = threadIdx.x;

    int v = (t < blockIdx.x) ? g_blksum[t] : 0;   // NBLK=196 < 512
    #pragma unroll
    for (int off = 16; off; off >>= 1) v += __shfl_down_sync(0xffffffffu, v, off);
    if ((t & 31) == 0) red[t >> 5] = v;
    __syncthreads();
    if (t < 32) {
        int s2 = (t < 16) ? red[t] : 0;
        #pragma unroll
        for (int off = 8; off; off >>= 1) s2 += __shfl_down_sync(0xffffffffu, s2, off);
        if (t == 0) pref = s2;
    }
    __syncthreads();

    int gid = blockIdx.x * SCAN_BLK + t;
    if (gid < NN) {
        int incl = g_rowptr[gid + 1] + pref;
        g_rowptr[gid + 1] = incl;
        int cnt = g_cnt[gid];
        g_cnt[gid] = 0;                          // self-clean for next replay
        g_pos[gid] = incl - cnt;
        g_dinv[gid] = rsqrtf((float)(cnt + 1));
    }
}

__global__ void k_fill(const int* __restrict__ ei) {
    int i = blockIdx.x * blockDim.x + threadIdx.x;
    if (i < EE) {
        int s = ei[i];
        int d = ei[EE + i];
        g_csr[atomicAdd(&g_pos[d], 1)] = s;
    }
}

// ---------------------------------------------------------------------------
// Split-bf16 tensor GEMM: bufA(bf16) = A @ W  (raw, NO dinv — applied in aggr).
#define SWZ(x) ((x) ^ (((x) >> 3) & 0x70))
#define S_AHI 0
#define S_ALO 32768
#define S_BHI 65536
#define S_BLO 98304
#define GEMM_SMEM 131072

__device__ __forceinline__ void cp16(uint32_t dst, const void* src, int srcsize) {
    asm volatile("cp.async.cg.shared.global [%0], [%1], 16, %2;"
                 :: "r"(dst), "l"(src), "r"(srcsize));
}

__device__ __forceinline__ void ldm4(uint32_t* r, uint32_t addr) {
    asm volatile("ldmatrix.sync.aligned.m8n8.x4.shared.b16 {%0,%1,%2,%3}, [%4];"
                 : "=r"(r[0]), "=r"(r[1]), "=r"(r[2]), "=r"(r[3]) : "r"(addr));
}

__device__ __forceinline__ void mma16816(float* c, const uint32_t* a, const uint32_t* b) {
    asm("mma.sync.aligned.m16n8k16.row.col.f32.bf16.bf16.f32 "
        "{%0,%1,%2,%3}, {%4,%5,%6,%7}, {%8,%9}, {%0,%1,%2,%3};"
        : "+f"(c[0]), "+f"(c[1]), "+f"(c[2]), "+f"(c[3])
        : "r"(a[0]), "r"(a[1]), "r"(a[2]), "r"(a[3]), "r"(b[0]), "r"(b[1]));
}

template<int LAYER>
__global__ void __launch_bounds__(256, 1)
k_gemm_mma() {
    extern __shared__ char smem[];
    uint32_t sb;
    { uint64_t tmp; asm("cvta.to.shared.u64 %0, %1;" : "=l"(tmp) : "l"(smem)); sb = (uint32_t)tmp; }

    const int t = threadIdx.x;
    const int wid = t >> 5;
    const int lid = t & 31;
    const int row0 = blockIdx.x * 128;
    const int warp_m = wid & 3;
    const int warp_n = wid >> 2;

    const __nv_bfloat16* Whi = (LAYER == 1) ? g_W1hi : g_W2hi;
    const __nv_bfloat16* Wlo = (LAYER == 1) ? g_W1lo : g_W2lo;

    #pragma unroll
    for (int arr = 0; arr < 2; arr++) {
        const __nv_bfloat16* Asrc = arr ? g_Alo : g_Ahi;
        const uint32_t abase = sb + (arr ? S_ALO : S_AHI);
        #pragma unroll
        for (int c = 0; c < 2; c++)
            #pragma unroll
            for (int i = 0; i < 4; i++) {
                int id = t + i * 256;
                int r  = id >> 3;
                int q  = id & 7;
                int grow = row0 + r;
                const void* g = Asrc + (size_t)grow * D + c * 64 + q * 8;
                cp16(abase + c * 16384 + SWZ((uint32_t)(r * 128 + q * 16)),
                     g, (grow < NN) ? 16 : 0);
            }
    }
    #pragma unroll
    for (int arr = 0; arr < 2; arr++) {
        const __nv_bfloat16* Bsrc = arr ? Wlo : Whi;
        const uint32_t bbase = sb + (arr ? S_BLO : S_BHI);
        #pragma unroll
        for (int c = 0; c < 2; c++)
            #pragma unroll
            for (int i = 0; i < 4; i++) {
                int id = t + i * 256;
                int n  = id >> 3;
                int q  = id & 7;
                cp16(bbase + c * 16384 + SWZ((uint32_t)(n * 128 + q * 16)),
                     Bsrc + n * D + c * 64 + q * 8, 16);
            }
    }
    asm volatile("cp.async.commit_group;");
    asm volatile("cp.async.wait_group 0;" ::: "memory");
    __syncthreads();

    float acc[2][8][4];
    #pragma unroll
    for (int i = 0; i < 2; i++)
        #pragma unroll
        for (int j = 0; j < 8; j++)
            #pragma unroll
            for (int q = 0; q < 4; q++) acc[i][j][q] = 0.0f;

    #pragma unroll
    for (int c = 0; c < 2; c++) {
        const uint32_t co = c * 16384;
        #pragma unroll
        for (int ks = 0; ks < 4; ks++) {
            uint32_t ah[2][4], al[2][4];
            #pragma unroll
            for (int mt = 0; mt < 2; mt++) {
                uint32_t off = SWZ((uint32_t)((warp_m * 32 + mt * 16 + (lid & 15)) * 128
                                              + ks * 32 + (lid >> 4) * 16));
                ldm4(ah[mt], sb + S_AHI + co + off);
                ldm4(al[mt], sb + S_ALO + co + off);
            }
            uint32_t bh[8][2], bl[8][2];
            #pragma unroll
            for (int ntp = 0; ntp < 4; ntp++) {
                uint32_t nrow = (lid & 7) + ((lid >> 4) & 1) * 8;
                uint32_t kb = ((lid >> 3) & 1) * 16;
                uint32_t off = SWZ((uint32_t)((warp_n * 64 + ntp * 16 + nrow) * 128
                                              + ks * 32 + kb));
                uint32_t r[4];
                ldm4(r, sb + S_BHI + co + off);
                bh[2 * ntp][0] = r[0]; bh[2 * ntp][1] = r[1];
                bh[2 * ntp + 1][0] = r[2]; bh[2 * ntp + 1][1] = r[3];
                ldm4(r, sb + S_BLO + co + off);
                bl[2 * ntp][0] = r[0]; bl[2 * ntp][1] = r[1];
                bl[2 * ntp + 1][0] = r[2]; bl[2 * ntp + 1][1] = r[3];
            }
            #pragma unroll
            for (int mt = 0; mt < 2; mt++)
                #pragma unroll
                for (int nt = 0; nt < 8; nt++) {
                    mma16816(acc[mt][nt], ah[mt], bh[nt]);
                    mma16816(acc[mt][nt], ah[mt], bl[nt]);
                    mma16816(acc[mt][nt], al[mt], bh[nt]);
                }
        }
    }

    // epilogue: store raw bf16 (dinv applied later in aggregation)
    const int g = lid >> 2, tig = lid & 3;
    #pragma unroll
    for (int mt = 0; mt < 2; mt++) {
        int m0 = row0 + warp_m * 32 + mt * 16 + g;
        int m8 = m0 + 8;
        #pragma unroll
        for (int nt = 0; nt < 8; nt++) {
            int col = warp_n * 64 + nt * 8 + tig * 2;
            if (m0 < NN)
                *reinterpret_cast<uint32_t*>(g_bufA + m0 * D + col) =
                    pack_bf2(acc[mt][nt][0], acc[mt][nt][1]);
            if (m8 < NN)
                *reinterpret_cast<uint32_t*>(g_bufA + m8 * D + col) =
                    pack_bf2(acc[mt][nt][2], acc[mt][nt][3]);
        }
    }
}

// ---------------------------------------------------------------------------
// CSR gather over raw bf16 messages; per-source dinv weighting inside loop.
// acc = dinv[n]*h[n] + sum dinv[s]*h[s];  r = dinv[n]*acc + b.
#define BF_FMA4(ds, u0, u1) \
    acc0 = fmaf(ds, __uint_as_float((u0) << 16), acc0);         \
    acc1 = fmaf(ds, __uint_as_float((u0) & 0xFFFF0000u), acc1); \
    acc2 = fmaf(ds, __uint_as_float((u1) << 16), acc2);         \
    acc3 = fmaf(ds, __uint_as_float((u1) & 0xFFFF0000u), acc3);

template<bool POOL>
__global__ void __launch_bounds__(256)
k_aggr(const int* __restrict__ batch, const float* __restrict__ bin) {
    int w = (blockIdx.x * blockDim.x + threadIdx.x) >> 5;
    int lane = threadIdx.x & 31;
    if (w >= NN) return;
    const int n = w;

    const uint2* src = reinterpret_cast<const uint2*>(g_bufA);
    const float dn = g_dinv[n];
    float acc0, acc1, acc2, acc3;
    {
        uint2 u = src[n * 32 + lane];
        acc0 = dn * __uint_as_float(u.x << 16);
        acc1 = dn * __uint_as_float(u.x & 0xFFFF0000u);
        acc2 = dn * __uint_as_float(u.y << 16);
        acc3 = dn * __uint_as_float(u.y & 0xFFFF0000u);
    }
    int beg = g_rowptr[n];
    int end = g_rowptr[n + 1];

    for (int base = beg; base < end; base += 32) {
        int idx = base + lane;
        int s_l = (idx < end) ? g_csr[idx] : 0;
        int cnt = min(32, end - base);
        int j = 0;
        for (; j + 4 <= cnt; j += 4) {
            int s0 = __shfl_sync(0xffffffffu, s_l, j);
            int s1 = __shfl_sync(0xffffffffu, s_l, j + 1);
            int s2 = __shfl_sync(0xffffffffu, s_l, j + 2);
            int s3 = __shfl_sync(0xffffffffu, s_l, j + 3);
            uint2 u0 = src[s0 * 32 + lane];
            uint2 u1 = src[s1 * 32 + lane];
            uint2 u2 = src[s2 * 32 + lane];
            uint2 u3 = src[s3 * 32 + lane];
            float d0 = __ldg(&g_dinv[s0]);
            float d1 = __ldg(&g_dinv[s1]);
            float d2 = __ldg(&g_dinv[s2]);
            float d3 = __ldg(&g_dinv[s3]);
            BF_FMA4(d0, u0.x, u0.y)
            BF_FMA4(d1, u1.x, u1.y)
            BF_FMA4(d2, u2.x, u2.y)
            BF_FMA4(d3, u3.x, u3.y)
        }
        for (; j < cnt; j++) {
            int s = __shfl_sync(0xffffffffu, s_l, j);
            uint2 u = src[s * 32 + lane];
            float ds = __ldg(&g_dinv[s]);
            BF_FMA4(ds, u.x, u.y)
        }
    }

    float4 bb = reinterpret_cast<const float4*>(bin)[lane];
    float r0 = fmaxf(fmaf(dn, acc0, bb.x), 0.f);
    float r1 = fmaxf(fmaf(dn, acc1, bb.y), 0.f);
    float r2 = fmaxf(fmaf(dn, acc2, bb.z), 0.f);
    float r3 = fmaxf(fmaf(dn, acc3, bb.w), 0.f);

    if (!POOL) {
        float h0 = __bfloat162float(__float2bfloat16_rn(r0));
        float h1 = __bfloat162float(__float2bfloat16_rn(r1));
        float h2 = __bfloat162float(__float2bfloat16_rn(r2));
        float h3 = __bfloat162float(__float2bfloat16_rn(r3));
        reinterpret_cast<uint2*>(g_Ahi)[n * 32 + lane] =
            make_uint2(pack_bf2(r0, r1), pack_bf2(r2, r3));
        reinterpret_cast<uint2*>(g_Alo)[n * 32 + lane] =
            make_uint2(pack_bf2(r0 - h0, r1 - h1), pack_bf2(r2 - h2, r3 - h3));
    } else {
        int g = batch[n];
        red_add_v4(g_pool + g * D + lane * 4, make_float4(r0, r1, r2, r3));
    }
}

// ---------------------------------------------------------------------------
__global__ void k_final(const float* __restrict__ Wl,
                        const float* __restrict__ bl,
                        float* __restrict__ out) {
    __shared__ float p[D];
    int g = blockIdx.x;
    int o = threadIdx.x;
    p[o]      = g_pool[g * D + o];
    p[o + 64] = g_pool[g * D + o + 64];
    g_pool[g * D + o]      = 0.0f;   // self-clean for next replay
    g_pool[g * D + o + 64] = 0.0f;
    __syncthreads();
    float acc = bl[o];
    #pragma unroll 8
    for (int c = 0; c < D; c++)
        acc = fmaf(p[c], Wl[c * OD + o], acc);
    out[g * OD + o] = acc;
}

// ---------------------------------------------------------------------------
extern "C" void kernel_launch(void* const* d_in, const int* in_sizes, int n_in,
                              void* d_out, int out_size) {
    const float* x     = (const float*)d_in[0];
    const int*   ei    = (const int*)d_in[1];      // int32 (JAX x64 disabled)
    const int*   batch = (const int*)d_in[2];
    const float* W1    = (const float*)d_in[3];
    const float* b1    = (const float*)d_in[4];
    const float* W2    = (const float*)d_in[5];
    const float* b2    = (const float*)d_in[6];
    const float* Wl    = (const float*)d_in[7];
    const float* bl    = (const float*)d_in[8];
    float* out = (float*)d_out;

    cudaFuncSetAttribute(k_gemm_mma<1>,
                         cudaFuncAttributeMaxDynamicSharedMemorySize, GEMM_SMEM);
    cudaFuncSetAttribute(k_gemm_mma<2>,
                         cudaFuncAttributeMaxDynamicSharedMemorySize, GEMM_SMEM);

    cudaStream_t side;
    cudaStreamCreateWithFlags(&side, cudaStreamNonBlocking);
    cudaEvent_t e0, e2;
    cudaEventCreateWithFlags(&e0, cudaEventDisableTiming);
    cudaEventCreateWithFlags(&e2, cudaEventDisableTiming);

    // Fork: side = dense chain (prep + GEMM1, no dinv dependency).
    cudaEventRecord(e0, 0);
    cudaStreamWaitEvent(side, e0, 0);
    k_prepxw<<<NB_PREPX + NB_PREPW, 256, 0, side>>>(x, W1, W2);
    k_gemm_mma<1><<<(NN + 127) / 128, 256, GEMM_SMEM, side>>>();
    cudaEventRecord(e2, side);

    // Main = CSR chain
    k_count<<<(EE + 255) / 256, 256>>>(ei);
    k_scan1<<<NBLK, SCAN_BLK>>>();
    k_scan3<<<NBLK, SCAN_BLK>>>();          // merged scan2+scan3
    k_fill<<<(EE + 255) / 256, 256>>>(ei);

    // Join: aggr1 needs csr+dinv (main) + bufA (side GEMM1)
    cudaStreamWaitEvent(0, e2, 0);
    k_aggr<false><<<(NN * 32 + 255) / 256, 256>>>(nullptr, b1);

    // Layer 2
    k_gemm_mma<2><<<(NN + 127) / 128, 256, GEMM_SMEM>>>();
    k_aggr<true><<<(NN * 32 + 255) / 256, 256>>>(batch, b2);

    k_final<<<NG, OD>>>(Wl, bl, out);

    cudaEventDestroy(e0);
    cudaEventDestroy(e2);
    cudaStreamDestroy(side);
}

// round 15
// speedup vs baseline: 1.0669x; 1.0669x over previous
#include <cuda_runtime.h>
#include <cuda_bf16.h>
#include <cstdint>

#define NN 100000
#define EE 1600000
#define D  128
#define OD 64
#define NG 512
#define SCAN_BLK 512
#define NBLK ((NN + SCAN_BLK - 1) / SCAN_BLK)   // 196
#define NSPLIT 64000                             // node split for GEMM2/aggr1 overlap

// Scratch (device globals: allocation-free)
__device__ __align__(16) __nv_bfloat16 g_bufA1[NN * D]; // layer-1 messages
__device__ __align__(16) __nv_bfloat16 g_bufA2[NN * D]; // layer-2 messages
__device__ __align__(16) __nv_bfloat16 g_Ahi[NN * D];   // GEMM A input hi
__device__ __align__(16) __nv_bfloat16 g_Alo[NN * D];   // GEMM A input lo
__device__ float g_dinv[NN];
__device__ __align__(16) float g_pool[NG * D];   // zeroed by k_final (self-clean)
__device__ int   g_cnt[NN];                      // zeroed by k_scan3 (self-clean)
__device__ int   g_pos[NN];
__device__ int   g_rowptr[NN + 1];
__device__ int   g_blksum[256];
__device__ int   g_csr[EE];
// Pre-transposed, bf16-split weights: [n*128 + k]
__device__ __align__(16) __nv_bfloat16 g_W1hi[D * D];
__device__ __align__(16) __nv_bfloat16 g_W1lo[D * D];
__device__ __align__(16) __nv_bfloat16 g_W2hi[D * D];
__device__ __align__(16) __nv_bfloat16 g_W2lo[D * D];

__device__ __forceinline__ void red_add_v4(float* addr, float4 v) {
    asm volatile("red.global.add.v4.f32 [%0], {%1,%2,%3,%4};"
                 :: "l"(__cvta_generic_to_global(addr)),
                    "f"(v.x), "f"(v.y), "f"(v.z), "f"(v.w)
                 : "memory");
}

__device__ __forceinline__ uint32_t pack_bf2(float a, float b) {
    __nv_bfloat162 t = __floats2bfloat162_rn(a, b);
    return *reinterpret_cast<uint32_t*>(&t);
}

// ---------------------------------------------------------------------------
__global__ void k_count(const int* __restrict__ ei) {
    int i = blockIdx.x * blockDim.x + threadIdx.x;
    if (i < EE) atomicAdd(&g_cnt[ei[EE + i]], 1);
}

#define NB_PREPX ((NN * D / 4 + 255) / 256)  // 12500
#define NB_PREPW 128

__global__ void k_prepxw(const float* __restrict__ x,
                         const float* __restrict__ W1, const float* __restrict__ W2) {
    int b = blockIdx.x;
    if (b < NB_PREPX) {
        int i = b * 256 + threadIdx.x;   // float4 index
        if (i < NN * D / 4) {
            float4 v = reinterpret_cast<const float4*>(x)[i];
            float hx = __bfloat162float(__float2bfloat16_rn(v.x));
            float hy = __bfloat162float(__float2bfloat16_rn(v.y));
            float hz = __bfloat162float(__float2bfloat16_rn(v.z));
            float hw = __bfloat162float(__float2bfloat16_rn(v.w));
            reinterpret_cast<uint2*>(g_Ahi)[i] =
                make_uint2(pack_bf2(v.x, v.y), pack_bf2(v.z, v.w));
            reinterpret_cast<uint2*>(g_Alo)[i] =
                make_uint2(pack_bf2(v.x - hx, v.y - hy), pack_bf2(v.z - hz, v.w - hw));
        }
    } else {
        int id = (b - NB_PREPX) * 256 + threadIdx.x;   // 0..32767
        int w = id >> 14;
        int r = id & 16383;
        int k = r >> 7, n = r & 127;
        float v = (w ? W2 : W1)[k * D + n];
        __nv_bfloat16 hi = __float2bfloat16_rn(v);
        __nv_bfloat16 lo = __float2bfloat16_rn(v - __bfloat162float(hi));
        (w ? g_W2hi : g_W1hi)[n * D + k] = hi;
        (w ? g_W2lo : g_W1lo)[n * D + k] = lo;
    }
}

// ---------------------------------------------------------------------------
__global__ void k_scan1() {
    __shared__ int s[SCAN_BLK];
    int gid = blockIdx.x * SCAN_BLK + threadIdx.x;
    int v = (gid < NN) ? g_cnt[gid] : 0;
    s[threadIdx.x] = v;
    __syncthreads();
    #pragma unroll
    for (int off = 1; off < SCAN_BLK; off <<= 1) {
        int t = (threadIdx.x >= off) ? s[threadIdx.x - off] : 0;
        __syncthreads();
        s[threadIdx.x] += t;
        __syncthreads();
    }
    if (gid < NN) g_rowptr[gid + 1] = s[threadIdx.x];
    if (threadIdx.x == SCAN_BLK - 1) g_blksum[blockIdx.x] = s[threadIdx.x];
    if (gid == 0) g_rowptr[0] = 0;
}

// scan3: per-block blksum prefix (merged scan2), rowptr/cursors/dinv; self-clean.
__global__ void k_scan3() {
    __shared__ int red[16];
    __shared__ int pref;
    int t = threadIdx.x;

    int v = (t < blockIdx.x) ? g_blksum[t] : 0;   // NBLK=196 < 512
    #pragma unroll
    for (int off = 16; off; off >>= 1) v += __shfl_down_sync(0xffffffffu, v, off);
    if ((t & 31) == 0) red[t >> 5] = v;
    __syncthreads();
    if (t < 32) {
        int s2 = (t < 16) ? red[t] : 0;
        #pragma unroll
        for (int off = 8; off; off >>= 1) s2 += __shfl_down_sync(0xffffffffu, s2, off);
        if (t == 0) pref = s2;
    }
    __syncthreads();

    int gid = blockIdx.x * SCAN_BLK + t;
    if (gid < NN) {
        int incl = g_rowptr[gid + 1] + pref;
        g_rowptr[gid + 1] = incl;
        int cnt = g_cnt[gid];
        g_cnt[gid] = 0;                          // self-clean for next replay
        g_pos[gid] = incl - cnt;
        g_dinv[gid] = rsqrtf((float)(cnt + 1));
    }
}

__global__ void k_fill(const int* __restrict__ ei) {
    int i = blockIdx.x * blockDim.x + threadIdx.x;
    if (i < EE) {
        int s = ei[i];
        int d = ei[EE + i];
        g_csr[atomicAdd(&g_pos[d], 1)] = s;
    }
}

// ---------------------------------------------------------------------------
// Split-bf16 tensor GEMM: msgbuf(bf16) = dinv[row] * (A @ W).
// LAYER 1 -> writes g_bufA1 (W1); LAYER 2 -> writes g_bufA2 (W2).
#define SWZ(x) ((x) ^ (((x) >> 3) & 0x70))
#define S_AHI 0
#define S_ALO 32768
#define S_BHI 65536
#define S_BLO 98304
#define GEMM_SMEM 131072

__device__ __forceinline__ void cp16(uint32_t dst, const void* src, int srcsize) {
    asm volatile("cp.async.cg.shared.global [%0], [%1], 16, %2;"
                 :: "r"(dst), "l"(src), "r"(srcsize));
}

__device__ __forceinline__ void ldm4(uint32_t* r, uint32_t addr) {
    asm volatile("ldmatrix.sync.aligned.m8n8.x4.shared.b16 {%0,%1,%2,%3}, [%4];"
                 : "=r"(r[0]), "=r"(r[1]), "=r"(r[2]), "=r"(r[3]) : "r"(addr));
}

__device__ __forceinline__ void mma16816(float* c, const uint32_t* a, const uint32_t* b) {
    asm("mma.sync.aligned.m16n8k16.row.col.f32.bf16.bf16.f32 "
        "{%0,%1,%2,%3}, {%4,%5,%6,%7}, {%8,%9}, {%0,%1,%2,%3};"
        : "+f"(c[0]), "+f"(c[1]), "+f"(c[2]), "+f"(c[3])
        : "r"(a[0]), "r"(a[1]), "r"(a[2]), "r"(a[3]), "r"(b[0]), "r"(b[1]));
}

template<int LAYER>
__global__ void __launch_bounds__(256, 1)
k_gemm_mma(int blk0) {
    extern __shared__ char smem[];
    uint32_t sb;
    { uint64_t tmp; asm("cvta.to.shared.u64 %0, %1;" : "=l"(tmp) : "l"(smem)); sb = (uint32_t)tmp; }

    const int t = threadIdx.x;
    const int wid = t >> 5;
    const int lid = t & 31;
    const int row0 = (blockIdx.x + blk0) * 128;
    const int warp_m = wid & 3;
    const int warp_n = wid >> 2;

    const __nv_bfloat16* Whi = (LAYER == 1) ? g_W1hi : g_W2hi;
    const __nv_bfloat16* Wlo = (LAYER == 1) ? g_W1lo : g_W2lo;
    __nv_bfloat16* dst = (LAYER == 1) ? g_bufA1 : g_bufA2;

    #pragma unroll
    for (int arr = 0; arr < 2; arr++) {
        const __nv_bfloat16* Asrc = arr ? g_Alo : g_Ahi;
        const uint32_t abase = sb + (arr ? S_ALO : S_AHI);
        #pragma unroll
        for (int c = 0; c < 2; c++)
            #pragma unroll
            for (int i = 0; i < 4; i++) {
                int id = t + i * 256;
                int r  = id >> 3;
                int q  = id & 7;
                int grow = row0 + r;
                const void* g = Asrc + (size_t)grow * D + c * 64 + q * 8;
                cp16(abase + c * 16384 + SWZ((uint32_t)(r * 128 + q * 16)),
                     g, (grow < NN) ? 16 : 0);
            }
    }
    #pragma unroll
    for (int arr = 0; arr < 2; arr++) {
        const __nv_bfloat16* Bsrc = arr ? Wlo : Whi;
        const uint32_t bbase = sb + (arr ? S_BLO : S_BHI);
        #pragma unroll
        for (int c = 0; c < 2; c++)
            #pragma unroll
            for (int i = 0; i < 4; i++) {
                int id = t + i * 256;
                int n  = id >> 3;
                int q  = id & 7;
                cp16(bbase + c * 16384 + SWZ((uint32_t)(n * 128 + q * 16)),
                     Bsrc + n * D + c * 64 + q * 8, 16);
            }
    }
    asm volatile("cp.async.commit_group;");
    asm volatile("cp.async.wait_group 0;" ::: "memory");
    __syncthreads();

    float acc[2][8][4];
    #pragma unroll
    for (int i = 0; i < 2; i++)
        #pragma unroll
        for (int j = 0; j < 8; j++)
            #pragma unroll
            for (int q = 0; q < 4; q++) acc[i][j][q] = 0.0f;

    #pragma unroll
    for (int c = 0; c < 2; c++) {
        const uint32_t co = c * 16384;
        #pragma unroll
        for (int ks = 0; ks < 4; ks++) {
            uint32_t ah[2][4], al[2][4];
            #pragma unroll
            for (int mt = 0; mt < 2; mt++) {
                uint32_t off = SWZ((uint32_t)((warp_m * 32 + mt * 16 + (lid & 15)) * 128
                                              + ks * 32 + (lid >> 4) * 16));
                ldm4(ah[mt], sb + S_AHI + co + off);
                ldm4(al[mt], sb + S_ALO + co + off);
            }
            uint32_t bh[8][2], bl[8][2];
            #pragma unroll
            for (int ntp = 0; ntp < 4; ntp++) {
                uint32_t nrow = (lid & 7) + ((lid >> 4) & 1) * 8;
                uint32_t kb = ((lid >> 3) & 1) * 16;
                uint32_t off = SWZ((uint32_t)((warp_n * 64 + ntp * 16 + nrow) * 128
                                              + ks * 32 + kb));
                uint32_t r[4];
                ldm4(r, sb + S_BHI + co + off);
                bh[2 * ntp][0] = r[0]; bh[2 * ntp][1] = r[1];
                bh[2 * ntp + 1][0] = r[2]; bh[2 * ntp + 1][1] = r[3];
                ldm4(r, sb + S_BLO + co + off);
                bl[2 * ntp][0] = r[0]; bl[2 * ntp][1] = r[1];
                bl[2 * ntp + 1][0] = r[2]; bl[2 * ntp + 1][1] = r[3];
            }
            #pragma unroll
            for (int mt = 0; mt < 2; mt++)
                #pragma unroll
                for (int nt = 0; nt < 8; nt++) {
                    mma16816(acc[mt][nt], ah[mt], bh[nt]);
                    mma16816(acc[mt][nt], ah[mt], bl[nt]);
                    mma16816(acc[mt][nt], al[mt], bh[nt]);
                }
        }
    }

    const int g = lid >> 2, tig = lid & 3;
    #pragma unroll
    for (int mt = 0; mt < 2; mt++) {
        int m0 = row0 + warp_m * 32 + mt * 16 + g;
        int m8 = m0 + 8;
        float dv0 = (m0 < NN) ? g_dinv[m0] : 0.f;
        float dv8 = (m8 < NN) ? g_dinv[m8] : 0.f;
        #pragma unroll
        for (int nt = 0; nt < 8; nt++) {
            int col = warp_n * 64 + nt * 8 + tig * 2;
            if (m0 < NN)
                *reinterpret_cast<uint32_t*>(dst + m0 * D + col) =
                    pack_bf2(acc[mt][nt][0] * dv0, acc[mt][nt][1] * dv0);
            if (m8 < NN)
                *reinterpret_cast<uint32_t*>(dst + m8 * D + col) =
                    pack_bf2(acc[mt][nt][2] * dv8, acc[mt][nt][3] * dv8);
        }
    }
}

// ---------------------------------------------------------------------------
// CSR gather over bf16 messages; shift/mask unpack. Warp per node, range [n0,n1).
// LAYER 1: reads g_bufA1, writes split Ahi/Alo (+b1,relu).
// LAYER 2: reads g_bufA2, pools (+b2,relu).
#define BF_ACC4(u0, u1) \
    acc0 += __uint_as_float((u0) << 16);        \
    acc1 += __uint_as_float((u0) & 0xFFFF0000u);\
    acc2 += __uint_as_float((u1) << 16);        \
    acc3 += __uint_as_float((u1) & 0xFFFF0000u);

template<int LAYER>
__global__ void __launch_bounds__(256)
k_aggr(const int* __restrict__ batch, const float* __restrict__ bin,
       int n0, int n1) {
    int w = n0 + ((blockIdx.x * blockDim.x + threadIdx.x) >> 5);
    int lane = threadIdx.x & 31;
    if (w >= n1) return;
    const int n = w;

    const uint2* src = reinterpret_cast<const uint2*>(LAYER == 1 ? g_bufA1 : g_bufA2);
    float acc0, acc1, acc2, acc3;
    {
        uint2 u = src[n * 32 + lane];
        acc0 = __uint_as_float(u.x << 16);
        acc1 = __uint_as_float(u.x & 0xFFFF0000u);
        acc2 = __uint_as_float(u.y << 16);
        acc3 = __uint_as_float(u.y & 0xFFFF0000u);
    }
    int beg = g_rowptr[n];
    int end = g_rowptr[n + 1];

    for (int base = beg; base < end; base += 32) {
        int idx = base + lane;
        int s_l = (idx < end) ? g_csr[idx] : 0;
        int cnt = min(32, end - base);
        int j = 0;
        for (; j + 4 <= cnt; j += 4) {
            int s0 = __shfl_sync(0xffffffffu, s_l, j);
            int s1 = __shfl_sync(0xffffffffu, s_l, j + 1);
            int s2 = __shfl_sync(0xffffffffu, s_l, j + 2);
            int s3 = __shfl_sync(0xffffffffu, s_l, j + 3);
            uint2 u0 = src[s0 * 32 + lane];
            uint2 u1 = src[s1 * 32 + lane];
            uint2 u2 = src[s2 * 32 + lane];
            uint2 u3 = src[s3 * 32 + lane];
            BF_ACC4(u0.x, u0.y)
            BF_ACC4(u1.x, u1.y)
            BF_ACC4(u2.x, u2.y)
            BF_ACC4(u3.x, u3.y)
        }
        for (; j < cnt; j++) {
            int s = __shfl_sync(0xffffffffu, s_l, j);
            uint2 u = src[s * 32 + lane];
            BF_ACC4(u.x, u.y)
        }
    }

    float dv = g_dinv[n];
    float4 bb = reinterpret_cast<const float4*>(bin)[lane];
    float r0 = fmaxf(fmaf(dv, acc0, bb.x), 0.f);
    float r1 = fmaxf(fmaf(dv, acc1, bb.y), 0.f);
    float r2 = fmaxf(fmaf(dv, acc2, bb.z), 0.f);
    float r3 = fmaxf(fmaf(dv, acc3, bb.w), 0.f);

    if (LAYER == 1) {
        float h0 = __bfloat162float(__float2bfloat16_rn(r0));
        float h1 = __bfloat162float(__float2bfloat16_rn(r1));
        float h2 = __bfloat162float(__float2bfloat16_rn(r2));
        float h3 = __bfloat162float(__float2bfloat16_rn(r3));
        reinterpret_cast<uint2*>(g_Ahi)[n * 32 + lane] =
            make_uint2(pack_bf2(r0, r1), pack_bf2(r2, r3));
        reinterpret_cast<uint2*>(g_Alo)[n * 32 + lane] =
            make_uint2(pack_bf2(r0 - h0, r1 - h1), pack_bf2(r2 - h2, r3 - h3));
    } else {
        int g = batch[n];
        red_add_v4(g_pool + g * D + lane * 4, make_float4(r0, r1, r2, r3));
    }
}

// ---------------------------------------------------------------------------
__global__ void k_final(const float* __restrict__ Wl,
                        const float* __restrict__ bl,
                        float* __restrict__ out) {
    __shared__ float p[D];
    int g = blockIdx.x;
    int o = threadIdx.x;
    p[o]      = g_pool[g * D + o];
    p[o + 64] = g_pool[g * D + o + 64];
    g_pool[g * D + o]      = 0.0f;   // self-clean for next replay
    g_pool[g * D + o + 64] = 0.0f;
    __syncthreads();
    float acc = bl[o];
    #pragma unroll 8
    for (int c = 0; c < D; c++)
        acc = fmaf(p[c], Wl[c * OD + o], acc);
    out[g * OD + o] = acc;
}

// ---------------------------------------------------------------------------
extern "C" void kernel_launch(void* const* d_in, const int* in_sizes, int n_in,
                              void* d_out, int out_size) {
    const float* x     = (const float*)d_in[0];
    const int*   ei    = (const int*)d_in[1];      // int32 (JAX x64 disabled)
    const int*   batch = (const int*)d_in[2];
    const float* W1    = (const float*)d_in[3];
    const float* b1    = (const float*)d_in[4];
    const float* W2    = (const float*)d_in[5];
    const float* b2    = (const float*)d_in[6];
    const float* Wl    = (const float*)d_in[7];
    const float* bl    = (const float*)d_in[8];
    float* out = (float*)d_out;

    cudaFuncSetAttribute(k_gemm_mma<1>,
                         cudaFuncAttributeMaxDynamicSharedMemorySize, GEMM_SMEM);
    cudaFuncSetAttribute(k_gemm_mma<2>,
                         cudaFuncAttributeMaxDynamicSharedMemorySize, GEMM_SMEM);

    cudaStream_t side;
    cudaStreamCreateWithFlags(&side, cudaStreamNonBlocking);
    cudaEvent_t e0, e1, e2, eA, eB;
    cudaEventCreateWithFlags(&e0, cudaEventDisableTiming);
    cudaEventCreateWithFlags(&e1, cudaEventDisableTiming);
    cudaEventCreateWithFlags(&e2, cudaEventDisableTiming);
    cudaEventCreateWithFlags(&eA, cudaEventDisableTiming);
    cudaEventCreateWithFlags(&eB, cudaEventDisableTiming);

    // Fork: side stream does dense prep concurrent with CSR build.
    cudaEventRecord(e0, 0);
    cudaStreamWaitEvent(side, e0, 0);
    k_prepxw<<<NB_PREPX + NB_PREPW, 256, 0, side>>>(x, W1, W2);

    // CSR chain on main stream
    k_count<<<(EE + 255) / 256, 256>>>(ei);
    k_scan1<<<NBLK, SCAN_BLK>>>();
    k_scan3<<<NBLK, SCAN_BLK>>>();
    cudaEventRecord(e1, 0);

    // GEMM1 on side (needs prepxw + dinv), concurrent with fill on main
    cudaStreamWaitEvent(side, e1, 0);
    k_gemm_mma<1><<<(NN + 127) / 128, 256, GEMM_SMEM, side>>>(0);
    cudaEventRecord(e2, side);

    k_fill<<<(EE + 255) / 256, 256>>>(ei);

    // Join, then split aggr1 so GEMM2A (writes bufA2, disjoint from bufA1 reads)
    // overlaps aggr1B.
    cudaStreamWaitEvent(0, e2, 0);
    k_aggr<1><<<(NSPLIT * 32 + 255) / 256, 256>>>(nullptr, b1, 0, NSPLIT);
    cudaEventRecord(eA, 0);

    // side: GEMM2 for rows [0, NSPLIT) — needs aggr1A's Ahi/Alo only
    cudaStreamWaitEvent(side, eA, 0);
    k_gemm_mma<2><<<NSPLIT / 128, 256, GEMM_SMEM, side>>>(0);
    cudaEventRecord(eB, side);

    // main: aggr1 tail, then GEMM2 for remaining rows
    k_aggr<1><<<((NN - NSPLIT) * 32 + 255) / 256, 256>>>(nullptr, b1, NSPLIT, NN);
    k_gemm_mma<2><<<(NN - NSPLIT + 127) / 128, 256, GEMM_SMEM>>>(NSPLIT / 128);

    // Join GEMM2A, then aggr2 (full, reads bufA2) + head
    cudaStreamWaitEvent(0, eB, 0);
    k_aggr<2><<<(NN * 32 + 255) / 256, 256>>>(batch, b2, 0, NN);
    k_final<<<NG, OD>>>(Wl, bl, out);

    cudaEventDestroy(e0);
    cudaEventDestroy(e1);
    cudaEventDestroy(e2);
    cudaEventDestroy(eA);
    cudaEventDestroy(eB);
    cudaStreamDestroy(side);
}

// round 16
// speedup vs baseline: 1.2538x; 1.1752x over previous
#include <cuda_runtime.h>
#include <cuda_bf16.h>
#include <cstdint>

#define NN 100000
#define EE 1600000
#define D  128
#define OD 64
#define NG 512
#define SCAN_BLK 512
#define NBLK ((NN + SCAN_BLK - 1) / SCAN_BLK)   // 196

// Scratch (device globals: allocation-free)
__device__ __align__(16) __nv_bfloat16 g_bufA1[NN * D]; // layer-1 messages
__device__ __align__(16) __nv_bfloat16 g_bufA2[NN * D]; // layer-2 messages
__device__ __align__(16) __nv_bfloat16 g_Ahi[NN * D];   // GEMM A input (hi only)
__device__ float g_dinv[NN];
__device__ __align__(16) float g_pool[NG * D];   // zeroed by k_final (self-clean)
__device__ int   g_cnt[NN];                      // zeroed by k_scan (self-clean)
__device__ int   g_pos[NN];
__device__ int   g_rowptr[NN + 1];
__device__ unsigned long long g_state[NBLK];     // lookback state; zeroed by k_fill
__device__ int   g_csr[EE];
// Pre-transposed, bf16-split weights: [n*128 + k]  (B side MUST stay split:
// weight rounding is coherent across the pool; A-side rounding washes out)
__device__ __align__(16) __nv_bfloat16 g_W1hi[D * D];
__device__ __align__(16) __nv_bfloat16 g_W1lo[D * D];
__device__ __align__(16) __nv_bfloat16 g_W2hi[D * D];
__device__ __align__(16) __nv_bfloat16 g_W2lo[D * D];

__device__ __forceinline__ void red_add_v4(float* addr, float4 v) {
    asm volatile("red.global.add.v4.f32 [%0], {%1,%2,%3,%4};"
                 :: "l"(__cvta_generic_to_global(addr)),
                    "f"(v.x), "f"(v.y), "f"(v.z), "f"(v.w)
                 : "memory");
}

__device__ __forceinline__ uint32_t pack_bf2(float a, float b) {
    __nv_bfloat162 t = __floats2bfloat162_rn(a, b);
    return *reinterpret_cast<uint32_t*>(&t);
}

// ---------------------------------------------------------------------------
__global__ void k_count(const int* __restrict__ ei) {
    int i = blockIdx.x * blockDim.x + threadIdx.x;
    if (i < EE) atomicAdd(&g_cnt[ei[EE + i]], 1);
}

#define NB_PREPX ((NN * D / 4 + 255) / 256)  // 12500
#define NB_PREPW 128

__global__ void k_prepxw(const float* __restrict__ x,
                         const float* __restrict__ W1, const float* __restrict__ W2) {
    int b = blockIdx.x;
    if (b < NB_PREPX) {
        int i = b * 256 + threadIdx.x;   // float4 index
        if (i < NN * D / 4) {
            float4 v = reinterpret_cast<const float4*>(x)[i];
            reinterpret_cast<uint2*>(g_Ahi)[i] =
                make_uint2(pack_bf2(v.x, v.y), pack_bf2(v.z, v.w));
        }
    } else {
        int id = (b - NB_PREPX) * 256 + threadIdx.x;   // 0..32767
        int w = id >> 14;
        int r = id & 16383;
        int k = r >> 7, n = r & 127;
        float v = (w ? W2 : W1)[k * D + n];
        __nv_bfloat16 hi = __float2bfloat16_rn(v);
        __nv_bfloat16 lo = __float2bfloat16_rn(v - __bfloat162float(hi));
        (w ? g_W2hi : g_W1hi)[n * D + k] = hi;
        (w ? g_W2lo : g_W1lo)[n * D + k] = lo;
    }
}

// ---------------------------------------------------------------------------
// Single-pass decoupled-lookback scan: block-local scan, publish {status|value}
// in one 8B word (status 1=aggregate, 2=inclusive prefix), warp lookback, then
// rowptr/cursors/dinv epilogue with g_cnt self-clean.
__global__ void k_scan() {
    __shared__ int s[SCAN_BLK];
    __shared__ int s_pref;
    const int t = threadIdx.x, b = blockIdx.x;
    int gid = b * SCAN_BLK + t;
    int cnt = (gid < NN) ? g_cnt[gid] : 0;
    s[t] = cnt;
    __syncthreads();
    #pragma unroll
    for (int off = 1; off < SCAN_BLK; off <<= 1) {
        int v = (t >= off) ? s[t - off] : 0;
        __syncthreads();
        s[t] += v;
        __syncthreads();
    }
    int incl_local = s[t];
    int bsum = s[SCAN_BLK - 1];

    if (t == 0) {
        unsigned long long pub = (b == 0)
            ? ((2ULL << 32) | (unsigned)bsum)
            : ((1ULL << 32) | (unsigned)bsum);
        asm volatile("st.volatile.global.u64 [%0], %1;"
                     :: "l"(&g_state[b]), "l"(pub) : "memory");
        if (b == 0) s_pref = 0;
    }
    if (b > 0 && t < 32) {
        int excl = 0;
        int idx = b - 1 - t;   // lane 0 = nearest predecessor
        for (;;) {
            unsigned long long v = 0;
            if (idx >= 0) {
                do {
                    asm volatile("ld.volatile.global.u64 %0, [%1];"
                                 : "=l"(v) : "l"(&g_state[idx]));
                } while ((unsigned)(v >> 32) == 0u);
            }
            unsigned st = (idx >= 0) ? (unsigned)(v >> 32) : 0u;
            int val = (int)(unsigned)(v & 0xffffffffu);
            unsigned pm = __ballot_sync(0xffffffffu, st == 2u);
            int contrib;
            bool done;
            if (pm) {
                int leader = __ffs(pm) - 1;   // smallest lane = nearest prefix
                contrib = (t <= leader) ? val : 0;
                done = true;
            } else {
                contrib = (st != 0u) ? val : 0;
                done = false;
            }
            #pragma unroll
            for (int o = 16; o; o >>= 1)
                contrib += __shfl_down_sync(0xffffffffu, contrib, o);
            if (t == 0) excl += contrib;
            if (done) break;
            idx -= 32;
        }
        if (t == 0) {
            unsigned long long pub = (2ULL << 32) | (unsigned)(excl + bsum);
            asm volatile("st.volatile.global.u64 [%0], %1;"
                         :: "l"(&g_state[b]), "l"(pub) : "memory");
            s_pref = excl;
        }
    }
    __syncthreads();
    int pref = s_pref;
    if (gid < NN) {
        int incl = incl_local + pref;
        g_rowptr[gid + 1] = incl;
        g_cnt[gid] = 0;                          // self-clean for next replay
        g_pos[gid] = incl - cnt;
        g_dinv[gid] = rsqrtf((float)(cnt + 1));
    }
    if (gid == 0) g_rowptr[0] = 0;
}

__global__ void k_fill(const int* __restrict__ ei) {
    int i = blockIdx.x * blockDim.x + threadIdx.x;
    if (i < NBLK) g_state[i] = 0ull;             // self-clean scan state
    if (i < EE) {
        int s = ei[i];
        int d = ei[EE + i];
        g_csr[atomicAdd(&g_pos[d], 1)] = s;
    }
}

// ---------------------------------------------------------------------------
// Split-bf16 GEMM, A = hi only: msgbuf(bf16) = dinv[row] * (Ahi @ (Whi+Wlo)).
// LAYER 1 -> g_bufA1 (W1); LAYER 2 -> g_bufA2 (W2).  96KB smem -> 2 CTA/SM.
#define SWZ(x) ((x) ^ (((x) >> 3) & 0x70))
#define S_AHI 0
#define S_BHI 32768
#define S_BLO 65536
#define GEMM_SMEM 98304

__device__ __forceinline__ void cp16(uint32_t dst, const void* src, int srcsize) {
    asm volatile("cp.async.cg.shared.global [%0], [%1], 16, %2;"
                 :: "r"(dst), "l"(src), "r"(srcsize));
}

__device__ __forceinline__ void ldm4(uint32_t* r, uint32_t addr) {
    asm volatile("ldmatrix.sync.aligned.m8n8.x4.shared.b16 {%0,%1,%2,%3}, [%4];"
                 : "=r"(r[0]), "=r"(r[1]), "=r"(r[2]), "=r"(r[3]) : "r"(addr));
}

__device__ __forceinline__ void mma16816(float* c, const uint32_t* a, const uint32_t* b) {
    asm("mma.sync.aligned.m16n8k16.row.col.f32.bf16.bf16.f32 "
        "{%0,%1,%2,%3}, {%4,%5,%6,%7}, {%8,%9}, {%0,%1,%2,%3};"
        : "+f"(c[0]), "+f"(c[1]), "+f"(c[2]), "+f"(c[3])
        : "r"(a[0]), "r"(a[1]), "r"(a[2]), "r"(a[3]), "r"(b[0]), "r"(b[1]));
}

template<int LAYER>
__global__ void __launch_bounds__(256, 2)
k_gemm_mma() {
    extern __shared__ char smem[];
    uint32_t sb;
    { uint64_t tmp; asm("cvta.to.shared.u64 %0, %1;" : "=l"(tmp) : "l"(smem)); sb = (uint32_t)tmp; }

    const int t = threadIdx.x;
    const int wid = t >> 5;
    const int lid = t & 31;
    const int row0 = blockIdx.x * 128;
    const int warp_m = wid & 3;
    const int warp_n = wid >> 2;

    const __nv_bfloat16* Whi = (LAYER == 1) ? g_W1hi : g_W2hi;
    const __nv_bfloat16* Wlo = (LAYER == 1) ? g_W1lo : g_W2lo;
    __nv_bfloat16* dst = (LAYER == 1) ? g_bufA1 : g_bufA2;

    // A (hi only): 32KB
    #pragma unroll
    for (int c = 0; c < 2; c++)
        #pragma unroll
        for (int i = 0; i < 4; i++) {
            int id = t + i * 256;
            int r  = id >> 3;
            int q  = id & 7;
            int grow = row0 + r;
            const void* g = g_Ahi + (size_t)grow * D + c * 64 + q * 8;
            cp16(sb + S_AHI + c * 16384 + SWZ((uint32_t)(r * 128 + q * 16)),
                 g, (grow < NN) ? 16 : 0);
        }
    // B (hi + lo): 64KB
    #pragma unroll
    for (int arr = 0; arr < 2; arr++) {
        const __nv_bfloat16* Bsrc = arr ? Wlo : Whi;
        const uint32_t bbase = sb + (arr ? S_BLO : S_BHI);
        #pragma unroll
        for (int c = 0; c < 2; c++)
            #pragma unroll
            for (int i = 0; i < 4; i++) {
                int id = t + i * 256;
                int n  = id >> 3;
                int q  = id & 7;
                cp16(bbase + c * 16384 + SWZ((uint32_t)(n * 128 + q * 16)),
                     Bsrc + n * D + c * 64 + q * 8, 16);
            }
    }
    asm volatile("cp.async.commit_group;");
    asm volatile("cp.async.wait_group 0;" ::: "memory");
    __syncthreads();

    float acc[2][8][4];
    #pragma unroll
    for (int i = 0; i < 2; i++)
        #pragma unroll
        for (int j = 0; j < 8; j++)
            #pragma unroll
            for (int q = 0; q < 4; q++) acc[i][j][q] = 0.0f;

    #pragma unroll
    for (int c = 0; c < 2; c++) {
        const uint32_t co = c * 16384;
        #pragma unroll
        for (int ks = 0; ks < 4; ks++) {
            uint32_t ah[2][4];
            #pragma unroll
            for (int mt = 0; mt < 2; mt++) {
                uint32_t off = SWZ((uint32_t)((warp_m * 32 + mt * 16 + (lid & 15)) * 128
                                              + ks * 32 + (lid >> 4) * 16));
                ldm4(ah[mt], sb + S_AHI + co + off);
            }
            uint32_t bh[8][2], bl[8][2];
            #pragma unroll
            for (int ntp = 0; ntp < 4; ntp++) {
                uint32_t nrow = (lid & 7) + ((lid >> 4) & 1) * 8;
                uint32_t kb = ((lid >> 3) & 1) * 16;
                uint32_t off = SWZ((uint32_t)((warp_n * 64 + ntp * 16 + nrow) * 128
                                              + ks * 32 + kb));
                uint32_t r[4];
                ldm4(r, sb + S_BHI + co + off);
                bh[2 * ntp][0] = r[0]; bh[2 * ntp][1] = r[1];
                bh[2 * ntp + 1][0] = r[2]; bh[2 * ntp + 1][1] = r[3];
                ldm4(r, sb + S_BLO + co + off);
                bl[2 * ntp][0] = r[0]; bl[2 * ntp][1] = r[1];
                bl[2 * ntp + 1][0] = r[2]; bl[2 * ntp + 1][1] = r[3];
            }
            #pragma unroll
            for (int mt = 0; mt < 2; mt++)
                #pragma unroll
                for (int nt = 0; nt < 8; nt++) {
                    mma16816(acc[mt][nt], ah[mt], bh[nt]);
                    mma16816(acc[mt][nt], ah[mt], bl[nt]);
                }
        }
    }

    const int g = lid >> 2, tig = lid & 3;
    #pragma unroll
    for (int mt = 0; mt < 2; mt++) {
        int m0 = row0 + warp_m * 32 + mt * 16 + g;
        int m8 = m0 + 8;
        float dv0 = (m0 < NN) ? g_dinv[m0] : 0.f;
        float dv8 = (m8 < NN) ? g_dinv[m8] : 0.f;
        #pragma unroll
        for (int nt = 0; nt < 8; nt++) {
            int col = warp_n * 64 + nt * 8 + tig * 2;
            if (m0 < NN)
                *reinterpret_cast<uint32_t*>(dst + m0 * D + col) =
                    pack_bf2(acc[mt][nt][0] * dv0, acc[mt][nt][1] * dv0);
            if (m8 < NN)
                *reinterpret_cast<uint32_t*>(dst + m8 * D + col) =
                    pack_bf2(acc[mt][nt][2] * dv8, acc[mt][nt][3] * dv8);
        }
    }
}

// ---------------------------------------------------------------------------
// CSR gather over bf16 messages; shift/mask unpack. Warp per node.
// LAYER 1: reads g_bufA1, writes g_Ahi (+b1,relu).  LAYER 2: pools (+b2,relu).
#define BF_ACC4(u0, u1) \
    acc0 += __uint_as_float((u0) << 16);        \
    acc1 += __uint_as_float((u0) & 0xFFFF0000u);\
    acc2 += __uint_as_float((u1) << 16);        \
    acc3 += __uint_as_float((u1) & 0xFFFF0000u);

template<int LAYER>
__global__ void __launch_bounds__(256)
k_aggr(const int* __restrict__ batch, const float* __restrict__ bin) {
    int w = (blockIdx.x * blockDim.x + threadIdx.x) >> 5;
    int lane = threadIdx.x & 31;
    if (w >= NN) return;
    const int n = w;

    const uint2* src = reinterpret_cast<const uint2*>(LAYER == 1 ? g_bufA1 : g_bufA2);
    float acc0, acc1, acc2, acc3;
    {
        uint2 u = src[n * 32 + lane];
        acc0 = __uint_as_float(u.x << 16);
        acc1 = __uint_as_float(u.x & 0xFFFF0000u);
        acc2 = __uint_as_float(u.y << 16);
        acc3 = __uint_as_float(u.y & 0xFFFF0000u);
    }
    int beg = g_rowptr[n];
    int end = g_rowptr[n + 1];

    for (int base = beg; base < end; base += 32) {
        int idx = base + lane;
        int s_l = (idx < end) ? g_csr[idx] : 0;
        int cnt = min(32, end - base);
        int j = 0;
        for (; j + 4 <= cnt; j += 4) {
            int s0 = __shfl_sync(0xffffffffu, s_l, j);
            int s1 = __shfl_sync(0xffffffffu, s_l, j + 1);
            int s2 = __shfl_sync(0xffffffffu, s_l, j + 2);
            int s3 = __shfl_sync(0xffffffffu, s_l, j + 3);
            uint2 u0 = src[s0 * 32 + lane];
            uint2 u1 = src[s1 * 32 + lane];
            uint2 u2 = src[s2 * 32 + lane];
            uint2 u3 = src[s3 * 32 + lane];
            BF_ACC4(u0.x, u0.y)
            BF_ACC4(u1.x, u1.y)
            BF_ACC4(u2.x, u2.y)
            BF_ACC4(u3.x, u3.y)
        }
        for (; j < cnt; j++) {
            int s = __shfl_sync(0xffffffffu, s_l, j);
            uint2 u = src[s * 32 + lane];
            BF_ACC4(u.x, u.y)
        }
    }

    float dv = g_dinv[n];
    float4 bb = reinterpret_cast<const float4*>(bin)[lane];
    float r0 = fmaxf(fmaf(dv, acc0, bb.x), 0.f);
    float r1 = fmaxf(fmaf(dv, acc1, bb.y), 0.f);
    float r2 = fmaxf(fmaf(dv, acc2, bb.z), 0.f);
    float r3 = fmaxf(fmaf(dv, acc3, bb.w), 0.f);

    if (LAYER == 1) {
        reinterpret_cast<uint2*>(g_Ahi)[n * 32 + lane] =
            make_uint2(pack_bf2(r0, r1), pack_bf2(r2, r3));
    } else {
        int g = batch[n];
        red_add_v4(g_pool + g * D + lane * 4, make_float4(r0, r1, r2, r3));
    }
}

// ---------------------------------------------------------------------------
__global__ void k_final(const float* __restrict__ Wl,
                        const float* __restrict__ bl,
                        float* __restrict__ out) {
    __shared__ float p[D];
    int g = blockIdx.x;
    int o = threadIdx.x;
    p[o]      = g_pool[g * D + o];
    p[o + 64] = g_pool[g * D + o + 64];
    g_pool[g * D + o]      = 0.0f;   // self-clean for next replay
    g_pool[g * D + o + 64] = 0.0f;
    __syncthreads();
    float acc = bl[o];
    #pragma unroll 8
    for (int c = 0; c < D; c++)
        acc = fmaf(p[c], Wl[c * OD + o], acc);
    out[g * OD + o] = acc;
}

// ---------------------------------------------------------------------------
extern "C" void kernel_launch(void* const* d_in, const int* in_sizes, int n_in,
                              void* d_out, int out_size) {
    const float* x     = (const float*)d_in[0];
    const int*   ei    = (const int*)d_in[1];      // int32 (JAX x64 disabled)
    const int*   batch = (const int*)d_in[2];
    const float* W1    = (const float*)d_in[3];
    const float* b1    = (const float*)d_in[4];
    const float* W2    = (const float*)d_in[5];
    const float* b2    = (const float*)d_in[6];
    const float* Wl    = (const float*)d_in[7];
    const float* bl    = (const float*)d_in[8];
    float* out = (float*)d_out;

    cudaFuncSetAttribute(k_gemm_mma<1>,
                         cudaFuncAttributeMaxDynamicSharedMemorySize, GEMM_SMEM);
    cudaFuncSetAttribute(k_gemm_mma<2>,
                         cudaFuncAttributeMaxDynamicSharedMemorySize, GEMM_SMEM);

    cudaStream_t side;
    cudaStreamCreateWithFlags(&side, cudaStreamNonBlocking);
    cudaEvent_t e0, e1, e2;
    cudaEventCreateWithFlags(&e0, cudaEventDisableTiming);
    cudaEventCreateWithFlags(&e1, cudaEventDisableTiming);
    cudaEventCreateWithFlags(&e2, cudaEventDisableTiming);

    // Fork: side stream does dense prep concurrent with CSR build.
    cudaEventRecord(e0, 0);
    cudaStreamWaitEvent(side, e0, 0);
    k_prepxw<<<NB_PREPX + NB_PREPW, 256, 0, side>>>(x, W1, W2);

    // CSR chain on main stream (single-pass lookback scan)
    k_count<<<(EE + 255) / 256, 256>>>(ei);
    k_scan<<<NBLK, SCAN_BLK>>>();
    cudaEventRecord(e1, 0);

    // GEMM1 on side (needs prepxw + dinv), concurrent with fill on main
    cudaStreamWaitEvent(side, e1, 0);
    k_gemm_mma<1><<<(NN + 127) / 128, 256, GEMM_SMEM, side>>>();
    cudaEventRecord(e2, side);

    k_fill<<<(EE + 255) / 256, 256>>>(ei);

    // Join, then linear: aggr1 -> GEMM2 -> aggr2 -> head
    cudaStreamWaitEvent(0, e2, 0);
    k_aggr<1><<<(NN * 32 + 255) / 256, 256>>>(nullptr, b1);
    k_gemm_mma<2><<<(NN + 127) / 128, 256, GEMM_SMEM>>>();
    k_aggr<2><<<(NN * 32 + 255) / 256, 256>>>(batch, b2);
    k_final<<<NG, OD>>>(Wl, bl, out);

    cudaEventDestroy(e0);
    cudaEventDestroy(e1);
    cudaEventDestroy(e2);
    cudaStreamDestroy(side);
}